// round 9
// baseline (speedup 1.0000x reference)
#include <cuda_runtime.h>
#include <cuda_bf16.h>
#include <cstdint>

// PhysicsRouter v9: L2 prefetch (1-phase-ahead, L2-fitting window) + GROUP=8
// for 2x warp concurrency. Fused finalize.
// logits = X @ W^T + mass*bias; softmax; top-2; aux loss.
// X [16384, 4096] f32, mass [16384], W [4, 4096], bias [4].
// Output (f32): [0,65536) logits | [65536,98304) top_k_idx | [98304] aux | [98305,131073) top_k_w
//
// Round 8 showed cp.async.bulk.prefetch.L2 breaks the per-SM demand-miss cap
// (DRAM 60%, best yet) but the 2-phase-ahead window (131MB) overflowed L2 and
// caused 50% re-fetch, and 1024 warps serialized the FMA consume side. Here:
// 1 phase ahead (67MB window, fits L2) and GROUP=8 (2048 warps).

#define C_DIM 4096
#define E_DIM 4
#define N_TOK 16384
#define GROUP 8                   // tokens per warp
#define WARPS_PER_BLOCK 8
#define BLOCK_THREADS (WARPS_PER_BLOCK * 32)
#define GRID_BLOCKS (N_TOK / (GROUP * WARPS_PER_BLOCK))   // 256
#define PHASES 4
#define ITERS_PER_PHASE 8         // 8 iters x 128 cols = 1024 floats = 4KB per row
#define PHASE_BYTES 4096

__device__ float g_partial[GRID_BLOCKS][E_DIM];
__device__ unsigned int g_count = 0;   // wraps to 0 each full grid -> graph-replay safe

__device__ __forceinline__ void l2_prefetch(const void* p, uint32_t bytes) {
    asm volatile("cp.async.bulk.prefetch.L2.global [%0], %1;"
                 :: "l"(p), "r"(bytes) : "memory");
}

__global__ void router_v9(const float* __restrict__ X,
                          const float* __restrict__ mass,
                          const float* __restrict__ W,
                          const float* __restrict__ bias,
                          float* __restrict__ out)
{
    const int tid   = threadIdx.x;
    const int warp  = tid >> 5;
    const int lane  = tid & 31;
    const int gwarp = blockIdx.x * WARPS_PER_BLOCK + warp;
    const long token0 = (long)gwarp * GROUP;

    // lane r (r < GROUP) prefetches row token0+r
    const float* myrow = X + (token0 + (lane & (GROUP - 1))) * (long)C_DIM;
    if (lane < GROUP)
        l2_prefetch(myrow, PHASE_BYTES);           // phase 0

    float acc[GROUP][E_DIM];
#pragma unroll
    for (int t = 0; t < GROUP; t++)
#pragma unroll
        for (int e = 0; e < E_DIM; e++) acc[t][e] = 0.0f;

    // 4 phases x 8 iterations x 128 columns. Prefetch next phase at the start
    // of each phase (steady window = GROUP x 4KB per warp = 32KB; x2048 warps
    // = 67MB, fits in 126MB L2).
#pragma unroll 1
    for (int ph = 0; ph < PHASES; ph++) {
        if (ph + 1 < PHASES && lane < GROUP)
            l2_prefetch(myrow + (ph + 1) * (PHASE_BYTES / 4), PHASE_BYTES);

#pragma unroll 1
        for (int i = 0; i < ITERS_PER_PHASE; i++) {
            const int col = (ph * ITERS_PER_PHASE + i) * 128 + lane * 4;
            const float4 g0 = __ldg((const float4*)(W + 0 * C_DIM + col));
            const float4 g1 = __ldg((const float4*)(W + 1 * C_DIM + col));
            const float4 g2 = __ldg((const float4*)(W + 2 * C_DIM + col));
            const float4 g3 = __ldg((const float4*)(W + 3 * C_DIM + col));
#pragma unroll
            for (int t = 0; t < GROUP; t++) {
                const float4 x = __ldg((const float4*)(X + (token0 + t) * C_DIM + col));
                acc[t][0] = fmaf(x.x, g0.x, fmaf(x.y, g0.y, fmaf(x.z, g0.z, fmaf(x.w, g0.w, acc[t][0]))));
                acc[t][1] = fmaf(x.x, g1.x, fmaf(x.y, g1.y, fmaf(x.z, g1.z, fmaf(x.w, g1.w, acc[t][1]))));
                acc[t][2] = fmaf(x.x, g2.x, fmaf(x.y, g2.y, fmaf(x.z, g2.z, fmaf(x.w, g2.w, acc[t][2]))));
                acc[t][3] = fmaf(x.x, g3.x, fmaf(x.y, g3.y, fmaf(x.z, g3.z, fmaf(x.w, g3.w, acc[t][3]))));
            }
        }
    }

    // Warp butterfly reduce all accumulators; every lane ends with full sums.
#pragma unroll
    for (int t = 0; t < GROUP; t++)
#pragma unroll
        for (int e = 0; e < E_DIM; e++)
#pragma unroll
            for (int s = 16; s > 0; s >>= 1)
                acc[t][e] += __shfl_xor_sync(0xFFFFFFFFu, acc[t][e], s);

    // Lane t (t < GROUP) takes token0 + t. Static-index selection.
    float l[E_DIM] = {0.f, 0.f, 0.f, 0.f};
#pragma unroll
    for (int t = 0; t < GROUP; t++) {
        if (lane == t) {
#pragma unroll
            for (int e = 0; e < E_DIM; e++) l[e] = acc[t][e];
        }
    }

    float p[E_DIM] = {0.f, 0.f, 0.f, 0.f};

    if (lane < GROUP) {
        const long token = token0 + lane;
        const float m = __ldg(mass + token);
        const float4 b = __ldg((const float4*)bias);
        l[0] = fmaf(m, b.x, l[0]);
        l[1] = fmaf(m, b.y, l[1]);
        l[2] = fmaf(m, b.z, l[2]);
        l[3] = fmaf(m, b.w, l[3]);

        float4 lo; lo.x = l[0]; lo.y = l[1]; lo.z = l[2]; lo.w = l[3];
        *(float4*)(out + token * E_DIM) = lo;

        const float mx = fmaxf(fmaxf(l[0], l[1]), fmaxf(l[2], l[3]));
        p[0] = expf(l[0] - mx);
        p[1] = expf(l[1] - mx);
        p[2] = expf(l[2] - mx);
        p[3] = expf(l[3] - mx);
        const float inv = 1.0f / (p[0] + p[1] + p[2] + p[3]);
        p[0] *= inv; p[1] *= inv; p[2] *= inv; p[3] *= inv;

        // top-2, lowest-index tie break (strict > keeps earlier index)
        int i1 = 0; float v1 = p[0];
#pragma unroll
        for (int e = 1; e < E_DIM; e++)
            if (p[e] > v1) { v1 = p[e]; i1 = e; }
        int i2 = -1; float v2 = -1.0f;
#pragma unroll
        for (int e = 0; e < E_DIM; e++)
            if (e != i1 && p[e] > v2) { v2 = p[e]; i2 = e; }

        float* out_idx = out + (long)N_TOK * E_DIM;
        float* out_w   = out + (long)N_TOK * E_DIM + (long)N_TOK * 2 + 1;
        out_idx[token * 2 + 0] = (float)i1;
        out_idx[token * 2 + 1] = (float)i2;
        out_w[token * 2 + 0]   = v1;
        out_w[token * 2 + 1]   = v2;
    }

    // ---- expert importance: warp reduce -> block partial -> counter ----
#pragma unroll
    for (int e = 0; e < E_DIM; e++)
#pragma unroll
        for (int s = 16; s > 0; s >>= 1)
            p[e] += __shfl_xor_sync(0xFFFFFFFFu, p[e], s);

    __shared__ float s_imp[WARPS_PER_BLOCK][E_DIM];
    if (lane == 0) {
#pragma unroll
        for (int e = 0; e < E_DIM; e++) s_imp[warp][e] = p[e];
    }
    __syncthreads();

    __shared__ bool s_is_last;
    if (tid == 0) {
        float pb[E_DIM] = {0.f, 0.f, 0.f, 0.f};
#pragma unroll
        for (int w = 0; w < WARPS_PER_BLOCK; w++)
#pragma unroll
            for (int e = 0; e < E_DIM; e++) pb[e] += s_imp[w][e];
#pragma unroll
        for (int e = 0; e < E_DIM; e++)
            g_partial[blockIdx.x][e] = pb[e];
        __threadfence();
        const unsigned int v = atomicInc(&g_count, GRID_BLOCKS - 1);
        s_is_last = (v == GRID_BLOCKS - 1);
    }
    __syncthreads();

    // ---- last block finalizes aux loss ----
    if (s_is_last) {
        __shared__ double s_sum[BLOCK_THREADS];
        const int e = tid & 3;
        const int chunk = tid >> 2;                           // 0..63
        const int per = GRID_BLOCKS / (BLOCK_THREADS / 4);    // 4
        double s = 0.0;
        for (int j = chunk * per; j < (chunk + 1) * per; j++)
            s += (double)g_partial[j][e];
        s_sum[tid] = s;
        __syncthreads();
        if (tid < E_DIM) {
            double imp = 0.0;
#pragma unroll
            for (int k = 0; k < BLOCK_THREADS / 4; k++)
                imp += s_sum[e + 4 * k];                      // e == tid here
            s_sum[tid] = imp;
        }
        __syncthreads();
        if (tid == 0) {
            const double target = (double)N_TOK / (double)E_DIM;
            double loss = 0.0;
#pragma unroll
            for (int k = 0; k < E_DIM; k++) {
                const double d = s_sum[k] - target;
                loss += d * d;
            }
            out[(long)N_TOK * E_DIM + (long)N_TOK * 2] = (float)(loss / E_DIM);
        }
    }
}

extern "C" void kernel_launch(void* const* d_in, const int* in_sizes, int n_in,
                              void* d_out, int out_size)
{
    const float* X    = (const float*)d_in[0];
    const float* mass = (const float*)d_in[1];
    const float* W    = (const float*)d_in[2];
    const float* bias = (const float*)d_in[3];
    float* out = (float*)d_out;

    router_v9<<<GRID_BLOCKS, BLOCK_THREADS>>>(X, mass, W, bias, out);
}

// round 10
// speedup vs baseline: 1.4392x; 1.4392x over previous
#include <cuda_runtime.h>
#include <cuda_bf16.h>
#include <cstdint>

// PhysicsRouter v10: round-1 demand-load mainloop (best useful-BW engine of
// all 9 rounds) + fused finalize + streaming X loads + fine-grained blocks.
// logits = X @ W^T + mass*bias; softmax; top-2; aux loss.
// X [16384, 4096] f32, mass [16384], W [4, 4096], bias [4].
// Output (f32): [0,65536) logits | [65536,98304) top_k_idx | [98304] aux | [98305,131073) top_k_w
//
// Post-mortems: smem pipelines cap at 46-48% (consumer barriers/latency),
// L2 prefetch inflates DRAM traffic 1.5-1.7x (prefetches arrive AFTER demand).
// Plain GROUP=16 demand loads gave 4.4 TB/s useful. Keep that engine; recover
// the 7us of helper-launch overhead; __ldcs X so it can't evict the L1-resident
// gate; 512x2-warp blocks for better tail balance than 256x4.

#define C_DIM 4096
#define E_DIM 4
#define N_TOK 16384
#define GROUP 16                  // tokens per warp
#define WARPS_PER_BLOCK 2
#define BLOCK_THREADS (WARPS_PER_BLOCK * 32)
#define GRID_BLOCKS (N_TOK / (GROUP * WARPS_PER_BLOCK))   // 512

__device__ float g_partial[GRID_BLOCKS][E_DIM];
__device__ unsigned int g_count = 0;   // wraps to 0 each full grid -> graph-replay safe

__global__ void router_v10(const float* __restrict__ X,
                           const float* __restrict__ mass,
                           const float* __restrict__ W,
                           const float* __restrict__ bias,
                           float* __restrict__ out)
{
    const int tid   = threadIdx.x;
    const int warp  = tid >> 5;
    const int lane  = tid & 31;
    const int gwarp = blockIdx.x * WARPS_PER_BLOCK + warp;
    const long token0 = (long)gwarp * GROUP;

    float acc[GROUP][E_DIM];
#pragma unroll
    for (int t = 0; t < GROUP; t++)
#pragma unroll
        for (int e = 0; e < E_DIM; e++) acc[t][e] = 0.0f;

    // 32 iterations x 128 columns. Gate float4s loaded once per iteration
    // (L1-resident, __ldg), X float4s streamed with evict-first (__ldcs).
#pragma unroll 1
    for (int it = 0; it < C_DIM / 128; ++it) {
        const int col = it * 128 + lane * 4;
        const float4 g0 = __ldg((const float4*)(W + 0 * C_DIM + col));
        const float4 g1 = __ldg((const float4*)(W + 1 * C_DIM + col));
        const float4 g2 = __ldg((const float4*)(W + 2 * C_DIM + col));
        const float4 g3 = __ldg((const float4*)(W + 3 * C_DIM + col));
#pragma unroll
        for (int t = 0; t < GROUP; t++) {
            const float4 x = __ldcs((const float4*)(X + (token0 + t) * C_DIM + col));
            acc[t][0] = fmaf(x.x, g0.x, fmaf(x.y, g0.y, fmaf(x.z, g0.z, fmaf(x.w, g0.w, acc[t][0]))));
            acc[t][1] = fmaf(x.x, g1.x, fmaf(x.y, g1.y, fmaf(x.z, g1.z, fmaf(x.w, g1.w, acc[t][1]))));
            acc[t][2] = fmaf(x.x, g2.x, fmaf(x.y, g2.y, fmaf(x.z, g2.z, fmaf(x.w, g2.w, acc[t][2]))));
            acc[t][3] = fmaf(x.x, g3.x, fmaf(x.y, g3.y, fmaf(x.z, g3.z, fmaf(x.w, g3.w, acc[t][3]))));
        }
    }

    // Warp butterfly reduce all 64 accumulators; every lane ends with full sums.
#pragma unroll
    for (int t = 0; t < GROUP; t++)
#pragma unroll
        for (int e = 0; e < E_DIM; e++)
#pragma unroll
            for (int s = 16; s > 0; s >>= 1)
                acc[t][e] += __shfl_xor_sync(0xFFFFFFFFu, acc[t][e], s);

    // Lane t (t < GROUP) takes token0 + t. Static-index selection.
    float l[E_DIM] = {0.f, 0.f, 0.f, 0.f};
#pragma unroll
    for (int t = 0; t < GROUP; t++) {
        if (lane == t) {
#pragma unroll
            for (int e = 0; e < E_DIM; e++) l[e] = acc[t][e];
        }
    }

    float p[E_DIM] = {0.f, 0.f, 0.f, 0.f};

    if (lane < GROUP) {
        const long token = token0 + lane;
        const float m = __ldg(mass + token);
        const float4 b = __ldg((const float4*)bias);
        l[0] = fmaf(m, b.x, l[0]);
        l[1] = fmaf(m, b.y, l[1]);
        l[2] = fmaf(m, b.z, l[2]);
        l[3] = fmaf(m, b.w, l[3]);

        float4 lo; lo.x = l[0]; lo.y = l[1]; lo.z = l[2]; lo.w = l[3];
        *(float4*)(out + token * E_DIM) = lo;

        const float mx = fmaxf(fmaxf(l[0], l[1]), fmaxf(l[2], l[3]));
        p[0] = expf(l[0] - mx);
        p[1] = expf(l[1] - mx);
        p[2] = expf(l[2] - mx);
        p[3] = expf(l[3] - mx);
        const float inv = 1.0f / (p[0] + p[1] + p[2] + p[3]);
        p[0] *= inv; p[1] *= inv; p[2] *= inv; p[3] *= inv;

        // top-2, lowest-index tie break (strict > keeps earlier index)
        int i1 = 0; float v1 = p[0];
#pragma unroll
        for (int e = 1; e < E_DIM; e++)
            if (p[e] > v1) { v1 = p[e]; i1 = e; }
        int i2 = -1; float v2 = -1.0f;
#pragma unroll
        for (int e = 0; e < E_DIM; e++)
            if (e != i1 && p[e] > v2) { v2 = p[e]; i2 = e; }

        float* out_idx = out + (long)N_TOK * E_DIM;
        float* out_w   = out + (long)N_TOK * E_DIM + (long)N_TOK * 2 + 1;
        out_idx[token * 2 + 0] = (float)i1;
        out_idx[token * 2 + 1] = (float)i2;
        out_w[token * 2 + 0]   = v1;
        out_w[token * 2 + 1]   = v2;
    }

    // ---- expert importance: warp reduce -> block partial -> counter ----
#pragma unroll
    for (int e = 0; e < E_DIM; e++)
#pragma unroll
        for (int s = 16; s > 0; s >>= 1)
            p[e] += __shfl_xor_sync(0xFFFFFFFFu, p[e], s);

    __shared__ float s_imp[WARPS_PER_BLOCK][E_DIM];
    if (lane == 0) {
#pragma unroll
        for (int e = 0; e < E_DIM; e++) s_imp[warp][e] = p[e];
    }
    __syncthreads();

    __shared__ bool s_is_last;
    if (tid == 0) {
#pragma unroll
        for (int e = 0; e < E_DIM; e++)
            g_partial[blockIdx.x][e] = s_imp[0][e] + s_imp[1][e];
        __threadfence();
        const unsigned int v = atomicInc(&g_count, GRID_BLOCKS - 1);
        s_is_last = (v == GRID_BLOCKS - 1);
    }
    __syncthreads();

    // ---- last block finalizes aux loss ----
    if (s_is_last) {
        __shared__ double s_sum[BLOCK_THREADS];
        const int e = tid & 3;
        const int chunk = tid >> 2;                           // 0..15
        const int per = GRID_BLOCKS / (BLOCK_THREADS / 4);    // 32
        double s = 0.0;
        for (int j = chunk * per; j < (chunk + 1) * per; j++)
            s += (double)g_partial[j][e];
        s_sum[tid] = s;
        __syncthreads();
        if (tid < E_DIM) {
            double imp = 0.0;
#pragma unroll
            for (int k = 0; k < BLOCK_THREADS / 4; k++)
                imp += s_sum[e + 4 * k];                      // e == tid here
            s_sum[tid] = imp;
        }
        __syncthreads();
        if (tid == 0) {
            const double target = (double)N_TOK / (double)E_DIM;
            double loss = 0.0;
#pragma unroll
            for (int k = 0; k < E_DIM; k++) {
                const double d = s_sum[k] - target;
                loss += d * d;
            }
            out[(long)N_TOK * E_DIM + (long)N_TOK * 2] = (float)(loss / E_DIM);
        }
    }
}

extern "C" void kernel_launch(void* const* d_in, const int* in_sizes, int n_in,
                              void* d_out, int out_size)
{
    const float* X    = (const float*)d_in[0];
    const float* mass = (const float*)d_in[1];
    const float* W    = (const float*)d_in[2];
    const float* bias = (const float*)d_in[3];
    float* out = (float*)d_out;

    router_v10<<<GRID_BLOCKS, BLOCK_THREADS>>>(X, mass, W, bias, out);
}

// round 11
// speedup vs baseline: 1.7803x; 1.2370x over previous
#include <cuda_runtime.h>
#include <cuda_bf16.h>
#include <cstdint>

// PhysicsRouter v11: GROUP=8 + register double-buffered X loads (software
// pipeline across iterations) + 2048 warps. Fused finalize.
// logits = X @ W^T + mass*bias; softmax; top-2; aux loss.
// X [16384, 4096] f32, mass [16384], W [4, 4096], bias [4].
// Output (f32): [0,65536) logits | [65536,98304) top_k_idx | [98304] aux | [98305,131073) top_k_w
//
// v10 (64us) alternated load-burst / 380cyc stall / FMA phases per warp with
// only ~7 warps/SM. Here acc shrinks to 32 regs (GROUP=8), freeing two 32-reg
// X buffers: iter i+1's loads are in flight while iter i's FMAs run, so the
// memory pipe never drains; warp count doubles to 2048 (~13.8/SM).

#define C_DIM 4096
#define E_DIM 4
#define N_TOK 16384
#define GROUP 8                   // tokens per warp
#define WARPS_PER_BLOCK 4
#define BLOCK_THREADS (WARPS_PER_BLOCK * 32)
#define GRID_BLOCKS (N_TOK / (GROUP * WARPS_PER_BLOCK))   // 512
#define NITERS (C_DIM / 128)      // 32

__device__ float g_partial[GRID_BLOCKS][E_DIM];
__device__ unsigned int g_count = 0;   // wraps to 0 each full grid -> graph-replay safe

__global__ void router_v11(const float* __restrict__ X,
                           const float* __restrict__ mass,
                           const float* __restrict__ W,
                           const float* __restrict__ bias,
                           float* __restrict__ out)
{
    const int tid   = threadIdx.x;
    const int warp  = tid >> 5;
    const int lane  = tid & 31;
    const int gwarp = blockIdx.x * WARPS_PER_BLOCK + warp;
    const long token0 = (long)gwarp * GROUP;
    const float* xw = X + token0 * (long)C_DIM + lane * 4;   // per-lane base

    float acc[GROUP][E_DIM];
#pragma unroll
    for (int t = 0; t < GROUP; t++)
#pragma unroll
        for (int e = 0; e < E_DIM; e++) acc[t][e] = 0.0f;

    float4 xa[GROUP], xb[GROUP];

    // preload iteration 0 into xa
#pragma unroll
    for (int t = 0; t < GROUP; t++)
        xa[t] = __ldcs((const float4*)(xw + (long)t * C_DIM));

    // mainloop, unrolled x2 with alternating X buffers. While FMAs consume one
    // buffer, the other buffer's 8 loads are in flight.
#pragma unroll 1
    for (int it = 0; it < NITERS; it += 2) {
        // issue loads for iteration it+1 into xb
        {
            const long off = (long)(it + 1) * 128;
#pragma unroll
            for (int t = 0; t < GROUP; t++)
                xb[t] = __ldcs((const float4*)(xw + (long)t * C_DIM + off));
        }
        // compute iteration it from xa
        {
            const int col = it * 128 + lane * 4;
            const float4 g0 = __ldg((const float4*)(W + 0 * C_DIM + col));
            const float4 g1 = __ldg((const float4*)(W + 1 * C_DIM + col));
            const float4 g2 = __ldg((const float4*)(W + 2 * C_DIM + col));
            const float4 g3 = __ldg((const float4*)(W + 3 * C_DIM + col));
#pragma unroll
            for (int t = 0; t < GROUP; t++) {
                const float4 x = xa[t];
                acc[t][0] = fmaf(x.x, g0.x, fmaf(x.y, g0.y, fmaf(x.z, g0.z, fmaf(x.w, g0.w, acc[t][0]))));
                acc[t][1] = fmaf(x.x, g1.x, fmaf(x.y, g1.y, fmaf(x.z, g1.z, fmaf(x.w, g1.w, acc[t][1]))));
                acc[t][2] = fmaf(x.x, g2.x, fmaf(x.y, g2.y, fmaf(x.z, g2.z, fmaf(x.w, g2.w, acc[t][2]))));
                acc[t][3] = fmaf(x.x, g3.x, fmaf(x.y, g3.y, fmaf(x.z, g3.z, fmaf(x.w, g3.w, acc[t][3]))));
            }
        }
        // issue loads for iteration it+2 into xa
        if (it + 2 < NITERS) {
            const long off = (long)(it + 2) * 128;
#pragma unroll
            for (int t = 0; t < GROUP; t++)
                xa[t] = __ldcs((const float4*)(xw + (long)t * C_DIM + off));
        }
        // compute iteration it+1 from xb
        {
            const int col = (it + 1) * 128 + lane * 4;
            const float4 g0 = __ldg((const float4*)(W + 0 * C_DIM + col));
            const float4 g1 = __ldg((const float4*)(W + 1 * C_DIM + col));
            const float4 g2 = __ldg((const float4*)(W + 2 * C_DIM + col));
            const float4 g3 = __ldg((const float4*)(W + 3 * C_DIM + col));
#pragma unroll
            for (int t = 0; t < GROUP; t++) {
                const float4 x = xb[t];
                acc[t][0] = fmaf(x.x, g0.x, fmaf(x.y, g0.y, fmaf(x.z, g0.z, fmaf(x.w, g0.w, acc[t][0]))));
                acc[t][1] = fmaf(x.x, g1.x, fmaf(x.y, g1.y, fmaf(x.z, g1.z, fmaf(x.w, g1.w, acc[t][1]))));
                acc[t][2] = fmaf(x.x, g2.x, fmaf(x.y, g2.y, fmaf(x.z, g2.z, fmaf(x.w, g2.w, acc[t][2]))));
                acc[t][3] = fmaf(x.x, g3.x, fmaf(x.y, g3.y, fmaf(x.z, g3.z, fmaf(x.w, g3.w, acc[t][3]))));
            }
        }
    }

    // Warp butterfly reduce all accumulators; every lane ends with full sums.
#pragma unroll
    for (int t = 0; t < GROUP; t++)
#pragma unroll
        for (int e = 0; e < E_DIM; e++)
#pragma unroll
            for (int s = 16; s > 0; s >>= 1)
                acc[t][e] += __shfl_xor_sync(0xFFFFFFFFu, acc[t][e], s);

    // Lane t (t < GROUP) takes token0 + t. Static-index selection.
    float l[E_DIM] = {0.f, 0.f, 0.f, 0.f};
#pragma unroll
    for (int t = 0; t < GROUP; t++) {
        if (lane == t) {
#pragma unroll
            for (int e = 0; e < E_DIM; e++) l[e] = acc[t][e];
        }
    }

    float p[E_DIM] = {0.f, 0.f, 0.f, 0.f};

    if (lane < GROUP) {
        const long token = token0 + lane;
        const float m = __ldg(mass + token);
        const float4 b = __ldg((const float4*)bias);
        l[0] = fmaf(m, b.x, l[0]);
        l[1] = fmaf(m, b.y, l[1]);
        l[2] = fmaf(m, b.z, l[2]);
        l[3] = fmaf(m, b.w, l[3]);

        float4 lo; lo.x = l[0]; lo.y = l[1]; lo.z = l[2]; lo.w = l[3];
        *(float4*)(out + token * E_DIM) = lo;

        const float mx = fmaxf(fmaxf(l[0], l[1]), fmaxf(l[2], l[3]));
        p[0] = expf(l[0] - mx);
        p[1] = expf(l[1] - mx);
        p[2] = expf(l[2] - mx);
        p[3] = expf(l[3] - mx);
        const float inv = 1.0f / (p[0] + p[1] + p[2] + p[3]);
        p[0] *= inv; p[1] *= inv; p[2] *= inv; p[3] *= inv;

        // top-2, lowest-index tie break (strict > keeps earlier index)
        int i1 = 0; float v1 = p[0];
#pragma unroll
        for (int e = 1; e < E_DIM; e++)
            if (p[e] > v1) { v1 = p[e]; i1 = e; }
        int i2 = -1; float v2 = -1.0f;
#pragma unroll
        for (int e = 0; e < E_DIM; e++)
            if (e != i1 && p[e] > v2) { v2 = p[e]; i2 = e; }

        float* out_idx = out + (long)N_TOK * E_DIM;
        float* out_w   = out + (long)N_TOK * E_DIM + (long)N_TOK * 2 + 1;
        out_idx[token * 2 + 0] = (float)i1;
        out_idx[token * 2 + 1] = (float)i2;
        out_w[token * 2 + 0]   = v1;
        out_w[token * 2 + 1]   = v2;
    }

    // ---- expert importance: warp reduce -> block partial -> counter ----
#pragma unroll
    for (int e = 0; e < E_DIM; e++)
#pragma unroll
        for (int s = 16; s > 0; s >>= 1)
            p[e] += __shfl_xor_sync(0xFFFFFFFFu, p[e], s);

    __shared__ float s_imp[WARPS_PER_BLOCK][E_DIM];
    if (lane == 0) {
#pragma unroll
        for (int e = 0; e < E_DIM; e++) s_imp[warp][e] = p[e];
    }
    __syncthreads();

    __shared__ bool s_is_last;
    if (tid == 0) {
        float pb[E_DIM] = {0.f, 0.f, 0.f, 0.f};
#pragma unroll
        for (int w = 0; w < WARPS_PER_BLOCK; w++)
#pragma unroll
            for (int e = 0; e < E_DIM; e++) pb[e] += s_imp[w][e];
#pragma unroll
        for (int e = 0; e < E_DIM; e++)
            g_partial[blockIdx.x][e] = pb[e];
        __threadfence();
        const unsigned int v = atomicInc(&g_count, GRID_BLOCKS - 1);
        s_is_last = (v == GRID_BLOCKS - 1);
    }
    __syncthreads();

    // ---- last block finalizes aux loss ----
    if (s_is_last) {
        __shared__ double s_sum[BLOCK_THREADS];
        const int e = tid & 3;
        const int chunk = tid >> 2;                           // 0..31
        const int per = GRID_BLOCKS / (BLOCK_THREADS / 4);    // 16
        double s = 0.0;
        for (int j = chunk * per; j < (chunk + 1) * per; j++)
            s += (double)g_partial[j][e];
        s_sum[tid] = s;
        __syncthreads();
        if (tid < E_DIM) {
            double imp = 0.0;
#pragma unroll
            for (int k = 0; k < BLOCK_THREADS / 4; k++)
                imp += s_sum[e + 4 * k];                      // e == tid here
            s_sum[tid] = imp;
        }
        __syncthreads();
        if (tid == 0) {
            const double target = (double)N_TOK / (double)E_DIM;
            double loss = 0.0;
#pragma unroll
            for (int k = 0; k < E_DIM; k++) {
                const double d = s_sum[k] - target;
                loss += d * d;
            }
            out[(long)N_TOK * E_DIM + (long)N_TOK * 2] = (float)(loss / E_DIM);
        }
    }
}

extern "C" void kernel_launch(void* const* d_in, const int* in_sizes, int n_in,
                              void* d_out, int out_size)
{
    const float* X    = (const float*)d_in[0];
    const float* mass = (const float*)d_in[1];
    const float* W    = (const float*)d_in[2];
    const float* bias = (const float*)d_in[3];
    float* out = (float*)d_out;

    router_v11<<<GRID_BLOCKS, BLOCK_THREADS>>>(X, mass, W, bias, out);
}